// round 16
// baseline (speedup 1.0000x reference)
#include <cuda_runtime.h>
#include <cuda_fp16.h>
#include <cstdint>

#define NSEQ  2048
#define HIDD  1024
#define NHEAD 16
#define HS    64
#define SAMPLED_ELEMS (16ULL * 2048ULL * 2048ULL)   // 67108864 floats
#define OUT4_TOTAL (SAMPLED_ELEMS / 4)              // 16777216 float4

// fp16 limb scratch
__device__ __half g_A0[3 * NSEQ * HIDD];
__device__ __half g_A1[3 * NSEQ * HIDD];
__device__ __half g_W0[3 * HIDD * HIDD];
__device__ __half g_W1[3 * HIDD * HIDD];
__device__ __half g_Q0[NSEQ * HIDD];
__device__ __half g_Q1[NSEQ * HIDD];
__device__ __half g_K0[NSEQ * HIDD];
__device__ __half g_K1[NSEQ * HIDD];

// ---------------- mma.sync / ldmatrix / cp.async helpers ----------------
__device__ __forceinline__ uint32_t smem_u32(const void* p) {
    uint32_t a;
    asm("{ .reg .u64 t; cvta.to.shared.u64 t, %1; cvt.u32.u64 %0, t; }" : "=r"(a) : "l"(p));
    return a;
}
__device__ __forceinline__ void ldsm4(uint32_t &r0, uint32_t &r1, uint32_t &r2,
                                      uint32_t &r3, uint32_t addr) {
    asm volatile("ldmatrix.sync.aligned.m8n8.x4.shared.b16 {%0,%1,%2,%3}, [%4];"
                 : "=r"(r0), "=r"(r1), "=r"(r2), "=r"(r3) : "r"(addr));
}
__device__ __forceinline__ void mma_f16(float &c0, float &c1, float &c2, float &c3,
                                        uint32_t a0, uint32_t a1, uint32_t a2, uint32_t a3,
                                        uint32_t b0, uint32_t b1) {
    asm volatile("mma.sync.aligned.m16n8k16.row.col.f32.f16.f16.f32 "
                 "{%0,%1,%2,%3}, {%4,%5,%6,%7}, {%8,%9}, {%0,%1,%2,%3};"
                 : "+f"(c0), "+f"(c1), "+f"(c2), "+f"(c3)
                 : "r"(a0), "r"(a1), "r"(a2), "r"(a3), "r"(b0), "r"(b1));
}
__device__ __forceinline__ void cp_async16(uint32_t dst, const void* src) {
    asm volatile("cp.async.cg.shared.global [%0], [%1], 16;" :: "r"(dst), "l"(src));
}
#define CP_COMMIT() asm volatile("cp.async.commit_group;" ::: "memory")
#define CP_WAIT0()  asm volatile("cp.async.wait_group 0;" ::: "memory")
#define CP_WAIT1()  asm volatile("cp.async.wait_group 1;" ::: "memory")

__device__ __forceinline__ void split16(float x, __half &h0, __half &h1) {
    h0 = __float2half(x);
    h1 = __float2half(x - __half2float(h0));
}

// =====================================================================
// Fused pre-pass: split activations + split/transpose weights.
// =====================================================================
__global__ void __launch_bounds__(256) split_all_kernel(
    const float* __restrict__ a0, const float* __restrict__ a1,
    const float* __restrict__ a2,
    const float* __restrict__ w0, const float* __restrict__ w1,
    const float* __restrict__ w2)
{
    const int bid = blockIdx.x;
    const int tid = threadIdx.x;

    if (bid < 6144) {
        const int mat = bid >> 11;
        const int row = bid & 2047;
        const float* src = (mat == 0) ? a0 : (mat == 1) ? a1 : a2;
        const size_t base = (size_t)mat * NSEQ * HIDD + (size_t)row * HIDD;
        float4 v = ((const float4*)(src + (size_t)row * HIDD))[tid];
        __half h0[4], h1[4];
        split16(v.x, h0[0], h1[0]);
        split16(v.y, h0[1], h1[1]);
        split16(v.z, h0[2], h1[2]);
        split16(v.w, h0[3], h1[3]);
        const size_t o = base + tid * 4;
        *(__half2*)&g_A0[o]     = __halves2half2(h0[0], h0[1]);
        *(__half2*)&g_A0[o + 2] = __halves2half2(h0[2], h0[3]);
        *(__half2*)&g_A1[o]     = __halves2half2(h1[0], h1[1]);
        *(__half2*)&g_A1[o + 2] = __halves2half2(h1[2], h1[3]);
    } else {
        __shared__ float t[32][33];
        const int wb = bid - 6144;
        const int mat = wb >> 10;
        const int rem = wb & 1023;
        const int n0 = (rem & 31) * 32, k0 = (rem >> 5) * 32;
        const float* W = (mat == 0) ? w0 : (mat == 1) ? w1 : w2;

        for (int i = tid; i < 1024; i += 256) {
            const int r = i >> 5, c = i & 31;
            t[r][c] = W[(size_t)(k0 + r) * HIDD + n0 + c];
        }
        __syncthreads();
        for (int i = tid; i < 1024; i += 256) {
            const int r = i >> 5, c = i & 31;
            const float x = t[c][r];
            __half h0, h1;
            split16(x, h0, h1);
            const size_t idx = (size_t)mat * HIDD * HIDD + (size_t)(n0 + r) * HIDD + k0 + c;
            g_W0[idx] = h0;
            g_W1[idx] = h1;
        }
    }
}

// =====================================================================
// Tensor-core fused 3x GEMM + interleaved one-hot zero-fill (the only
// overlap that works in this harness). Q/K: fp16 2-limb, 3 products.
// V (mat 2): single product a0*b0 (err ~2e-4 rel, under 1e-3 threshold).
// CTA 128x128, k-tile 32, triple-buffered cp.async.
// =====================================================================
#define GTILE 10240
#define GBUF  20480
#define GSTAGE 3
#define GEMM_SMEM (2 * GSTAGE * GBUF)    // 122880

__global__ void __launch_bounds__(256, 1) gemm3_tc_kernel(
    const float* __restrict__ bq, const float* __restrict__ bk,
    const float* __restrict__ bv, float* __restrict__ out)
{
    extern __shared__ char smem[];
    const uint32_t sb = smem_u32(smem);
    const int tid = threadIdx.x;
    const int lane = tid & 31, warp = tid >> 5;
    const int mat = blockIdx.z;
    const int row0 = blockIdx.y * 128, col0 = blockIdx.x * 128;

    const __half* A0 = g_A0 + (size_t)mat * NSEQ * HIDD;
    const __half* A1 = g_A1 + (size_t)mat * NSEQ * HIDD;
    const __half* B0 = g_W0 + (size_t)mat * HIDD * HIDD;
    const __half* B1 = g_W1 + (size_t)mat * HIDD * HIDD;
    const float* bias = (mat == 0) ? bq : (mat == 1) ? bk : bv;
    float* Cv = out + SAMPLED_ELEMS;
    const int nlimb = (mat == 2) ? 1 : 2;    // V: single limb/product
    const int nprod = (mat == 2) ? 1 : 3;

    // zero-fill assignment: global thread id over 384 CTAs x 256 thr
    const uint32_t gtid = ((blockIdx.z * gridDim.y + blockIdx.y) * gridDim.x
                           + blockIdx.x) * 256 + tid;
    const uint32_t zstride = 384 * 256;            // 98304
    float4* o4 = (float4*)out;
    const float4 zval = make_float4(0.f, 0.f, 0.f, 0.f);

    auto load_tile = [&](int kt, int stage) {
        const int k0 = kt * 32;
        for (int s = 0; s < nlimb; s++) {
            const __half* src = (s ? A1 : A0) + (size_t)row0 * HIDD + k0;
            const uint32_t dst = sb + stage * GBUF + s * GTILE;
            for (int i = tid; i < 512; i += 256) {
                const int r = i >> 2, c = i & 3;
                cp_async16(dst + r * 80 + c * 16, src + (size_t)r * HIDD + c * 8);
            }
        }
        for (int s = 0; s < nlimb; s++) {
            const __half* src = (s ? B1 : B0) + (size_t)col0 * HIDD + k0;
            const uint32_t dst = sb + GSTAGE * GBUF + stage * GBUF + s * GTILE;
            for (int i = tid; i < 512; i += 256) {
                const int r = i >> 2, c = i & 3;
                cp_async16(dst + r * 80 + c * 16, src + (size_t)r * HIDD + c * 8);
            }
        }
        CP_COMMIT();
    };

    const int mwarp = warp >> 1, nwarp = warp & 1;
    const uint32_t a_lane = (lane & 15) * 80 + (lane >> 4) * 16;
    const uint32_t b_lane = ((lane & 7) + ((lane >> 4) << 3)) * 80 + ((lane >> 3) & 1) * 16;

    float acc[2][8][4];
#pragma unroll
    for (int mb = 0; mb < 2; mb++)
#pragma unroll
        for (int nb = 0; nb < 8; nb++)
#pragma unroll
            for (int e = 0; e < 4; e++) acc[mb][nb][e] = 0.0f;

    const int pa[3] = {0, 0, 1};
    const int pb[3] = {0, 1, 0};

    load_tile(0, 0);
    load_tile(1, 1);
    for (int t = 0; t < 32; t++) {
        const int stage = t % GSTAGE;
        CP_WAIT1();
        __syncthreads();
        if (t + 2 < 32) load_tile(t + 2, (t + 2) % GSTAGE);

        // interleaved streaming zero-fill: 6 chunks per iteration
        {
            uint32_t zi = gtid + (uint32_t)t * 6 * zstride;
#pragma unroll
            for (int z = 0; z < 6; z++) {
                if (zi < OUT4_TOTAL) __stcs(&o4[zi], zval);
                zi += zstride;
            }
        }

        const uint32_t Ab = sb + stage * GBUF;
        const uint32_t Bb = sb + GSTAGE * GBUF + stage * GBUF;
#pragma unroll
        for (int ks = 0; ks < 2; ks++) {
            uint32_t a[2][2][4];
            for (int s = 0; s < nlimb; s++)
#pragma unroll
                for (int mb = 0; mb < 2; mb++)
                    ldsm4(a[s][mb][0], a[s][mb][1], a[s][mb][2], a[s][mb][3],
                          Ab + s * GTILE + (mwarp * 32 + mb * 16) * 80 + a_lane + ks * 32);
            uint32_t b[2][4][4];
            for (int s = 0; s < nlimb; s++)
#pragma unroll
                for (int jj = 0; jj < 4; jj++)
                    ldsm4(b[s][jj][0], b[s][jj][1], b[s][jj][2], b[s][jj][3],
                          Bb + s * GTILE + (nwarp * 64 + jj * 16) * 80 + b_lane + ks * 32);
            for (int p = 0; p < nprod; p++) {
#pragma unroll
                for (int mb = 0; mb < 2; mb++) {
                    const uint32_t* A = a[pa[p]][mb];
#pragma unroll
                    for (int jj = 0; jj < 4; jj++) {
                        mma_f16(acc[mb][2*jj][0], acc[mb][2*jj][1],
                                acc[mb][2*jj][2], acc[mb][2*jj][3],
                                A[0], A[1], A[2], A[3],
                                b[pb[p]][jj][0], b[pb[p]][jj][1]);
                        mma_f16(acc[mb][2*jj+1][0], acc[mb][2*jj+1][1],
                                acc[mb][2*jj+1][2], acc[mb][2*jj+1][3],
                                A[0], A[1], A[2], A[3],
                                b[pb[p]][jj][2], b[pb[p]][jj][3]);
                    }
                }
            }
        }
    }

    // ---- epilogue ----
    __half* S0 = (mat == 0) ? g_Q0 : g_K0;
    __half* S1 = (mat == 0) ? g_Q1 : g_K1;
#pragma unroll
    for (int mb = 0; mb < 2; mb++) {
        const int rbase = row0 + mwarp * 32 + mb * 16 + (lane >> 2);
#pragma unroll
        for (int hrow = 0; hrow < 2; hrow++) {
            const int r = rbase + hrow * 8;
#pragma unroll
            for (int nb = 0; nb < 8; nb++) {
                const int col = col0 + nwarp * 64 + nb * 8 + (lane & 3) * 2;
                const float2 bb = *(const float2*)&bias[col];
                const float x0 = acc[mb][nb][hrow * 2 + 0] + bb.x;
                const float x1 = acc[mb][nb][hrow * 2 + 1] + bb.y;
                if (mat == 2) {
                    *(float2*)&Cv[(size_t)r * HIDD + col] = make_float2(x0, x1);
                } else {
                    __half h00, h01, h10, h11;
                    split16(x0, h00, h01);
                    split16(x1, h10, h11);
                    const size_t idx = (size_t)r * HIDD + col;
                    *(__half2*)&S0[idx] = __halves2half2(h00, h10);
                    *(__half2*)&S1[idx] = __halves2half2(h01, h11);
                }
            }
        }
    }
}

// =====================================================================
// mma.sync attention: 512 threads (16 warps, 4/SMSP), 128 q rows/CTA.
// Warp (qw, kh): qw owns 16 q rows, kh owns 64 of 128 keys per tile.
// fp16 2-split, 3 products; double-buffered K via cp.async.
// Writes the one-hot 1.0 directly (zero-fill done earlier in-stream).
// =====================================================================
#define SPLIT_BYTES (128 * 144)
#define KBUF_BYTES  (2 * SPLIT_BYTES)     // 36864
#define ATTN_SMEM   (2 * KBUF_BYTES)      // 73728

__global__ void __launch_bounds__(512, 1) attn_mma_kernel(float* __restrict__ out)
{
    extern __shared__ char smem[];
    const uint32_t sb = smem_u32(smem);
    const int tid = threadIdx.x;
    const int lane = tid & 31, warp = tid >> 5;
    const int qw = warp >> 1, kh = warp & 1;
    const int h = blockIdx.y, q0 = blockIdx.x * 128;

    const __half* Qs[2] = {g_Q0 + (size_t)h * 131072 + (size_t)q0 * HS,
                           g_Q1 + (size_t)h * 131072 + (size_t)q0 * HS};
    const __half* Ks[2] = {g_K0 + (size_t)h * 131072,
                           g_K1 + (size_t)h * 131072};

    // stage Q into the (currently free) K-buffer area, pull A frags
#pragma unroll
    for (int s = 0; s < 2; s++) {
        for (int i = tid; i < 1024; i += 512) {
            const int row = i >> 3, c = i & 7;
            uint4 v = *(const uint4*)(Qs[s] + (size_t)row * HS + c * 8);
            *(uint4*)(smem + s * SPLIT_BYTES + row * 144 + c * 16) = v;
        }
    }
    __syncthreads();

    uint32_t afr[2][4][4];   // [split][ks][frag]
    {
        const uint32_t aoff = sb + (qw * 16 + (lane & 15)) * 144 + (lane >> 4) * 16;
#pragma unroll
        for (int s = 0; s < 2; s++)
#pragma unroll
            for (int ks = 0; ks < 4; ks++)
                ldsm4(afr[s][ks][0], afr[s][ks][1], afr[s][ks][2], afr[s][ks][3],
                      aoff + s * SPLIT_BYTES + ks * 32);
    }
    __syncthreads();

    auto load_k = [&](int kt, int buf) {
#pragma unroll
        for (int s = 0; s < 2; s++) {
            const __half* src = Ks[s] + (size_t)kt * 128 * HS;
            const uint32_t dst = sb + buf * KBUF_BYTES + s * SPLIT_BYTES;
            for (int i = tid; i < 1024; i += 512) {
                const int row = i >> 3, c = i & 7;
                cp_async16(dst + row * 144 + c * 16, src + (size_t)row * HS + c * 8);
            }
        }
        CP_COMMIT();
    };

    load_k(0, 0);
    CP_WAIT0();
    __syncthreads();

    const uint32_t boff_lane = ((lane & 7) + ((lane >> 4) << 3)) * 144
                             + (((lane >> 3) & 1)) * 16
                             + kh * 64 * 144;

    const int l4 = lane >> 2, l2 = (lane & 3) * 2;
    float best_lo = -__int_as_float(0x7f800000), best_hi = best_lo;
    int idx_lo = 0, idx_hi = 0;

    const int pa[3] = {0, 0, 1};
    const int pb[3] = {0, 1, 0};

    for (int kt = 0; kt < 16; kt++) {
        const int buf = kt & 1;
        if (kt < 15) load_k(kt + 1, buf ^ 1);

        float acc[8][4];
#pragma unroll
        for (int nb = 0; nb < 8; nb++)
#pragma unroll
            for (int e = 0; e < 4; e++) acc[nb][e] = 0.0f;

        const uint32_t bbase = sb + buf * KBUF_BYTES + boff_lane;

#pragma unroll
        for (int ks = 0; ks < 4; ks++) {
#pragma unroll
            for (int jh = 0; jh < 2; jh++) {
                uint32_t B[2][2][4];   // [split][jj][frag]
#pragma unroll
                for (int s = 0; s < 2; s++)
#pragma unroll
                    for (int jj = 0; jj < 2; jj++)
                        ldsm4(B[s][jj][0], B[s][jj][1], B[s][jj][2], B[s][jj][3],
                              bbase + s * SPLIT_BYTES + (jh * 2 + jj) * 16 * 144 + ks * 32);
#pragma unroll
                for (int p = 0; p < 3; p++) {
                    const uint32_t* A = afr[pa[p]][ks];
#pragma unroll
                    for (int jj = 0; jj < 2; jj++) {
                        const int j = jh * 2 + jj;
                        mma_f16(acc[2*j][0], acc[2*j][1], acc[2*j][2], acc[2*j][3],
                                A[0], A[1], A[2], A[3], B[pb[p]][jj][0], B[pb[p]][jj][1]);
                        mma_f16(acc[2*j+1][0], acc[2*j+1][1], acc[2*j+1][2], acc[2*j+1][3],
                                A[0], A[1], A[2], A[3], B[pb[p]][jj][2], B[pb[p]][jj][3]);
                    }
                }
            }
        }

        // running argmax over this warp's 64-key half
#pragma unroll
        for (int nb = 0; nb < 8; nb++) {
            const int col = kt * 128 + kh * 64 + nb * 8 + l2;
            if (acc[nb][0] > best_lo) { best_lo = acc[nb][0]; idx_lo = col; }
            if (acc[nb][1] > best_lo) { best_lo = acc[nb][1]; idx_lo = col + 1; }
            if (acc[nb][2] > best_hi) { best_hi = acc[nb][2]; idx_hi = col; }
            if (acc[nb][3] > best_hi) { best_hi = acc[nb][3]; idx_hi = col + 1; }
        }

        if (kt < 15) { CP_WAIT0(); __syncthreads(); }
    }

    // reduce over the 4 lanes sharing each q row (within this warp's half)
#pragma unroll
    for (int off = 1; off <= 2; off <<= 1) {
        float v2 = __shfl_xor_sync(0xffffffffu, best_lo, off);
        int   i2 = __shfl_xor_sync(0xffffffffu, idx_lo, off);
        if (v2 > best_lo || (v2 == best_lo && i2 < idx_lo)) { best_lo = v2; idx_lo = i2; }
        v2 = __shfl_xor_sync(0xffffffffu, best_hi, off);
        i2 = __shfl_xor_sync(0xffffffffu, idx_hi, off);
        if (v2 > best_hi || (v2 == best_hi && i2 < idx_hi)) { best_hi = v2; idx_hi = i2; }
    }

    // merge the two key-halves via smem (K buffers fully consumed)
    __syncthreads();
    float* sval = (float*)smem;               // [2][128]
    int*   sidx = (int*)(smem + 1024);        // [2][128]
    if ((lane & 3) == 0) {
        const int row = qw * 16 + l4;
        sval[kh * 128 + row]     = best_lo;
        sidx[kh * 128 + row]     = idx_lo;
        sval[kh * 128 + row + 8] = best_hi;
        sidx[kh * 128 + row + 8] = idx_hi;
    }
    __syncthreads();
    if (tid < 128) {
        const float v0 = sval[tid], v1 = sval[128 + tid];
        const int   i0 = sidx[tid], i1 = sidx[128 + tid];
        const int best = (v1 > v0 || (v1 == v0 && i1 < i0)) ? i1 : i0;
        // zero-fill completed earlier on this stream (inside gemm)
        out[((size_t)h * NSEQ + q0 + tid) * NSEQ + best] = 1.0f;
    }
}

// ---------------- launch (single stream, serial — forks don't overlap) --
extern "C" void kernel_launch(void* const* d_in, const int* in_sizes, int n_in,
                              void* d_out, int out_size)
{
    const float* q_in = (const float*)d_in[0];
    const float* k_in = (const float*)d_in[1];
    const float* v_in = (const float*)d_in[2];
    const float* Wq   = (const float*)d_in[4];
    const float* bq   = (const float*)d_in[5];
    const float* Wk   = (const float*)d_in[6];
    const float* bk   = (const float*)d_in[7];
    const float* Wv   = (const float*)d_in[8];
    const float* bv   = (const float*)d_in[9];
    float* out = (float*)d_out;

    static bool init = false;
    if (!init) {
        cudaFuncSetAttribute(gemm3_tc_kernel,
                             cudaFuncAttributeMaxDynamicSharedMemorySize, GEMM_SMEM);
        cudaFuncSetAttribute(attn_mma_kernel,
                             cudaFuncAttributeMaxDynamicSharedMemorySize, ATTN_SMEM);
        init = true;
    }

    split_all_kernel<<<9216, 256>>>(q_in, k_in, v_in, Wq, Wk, Wv);

    dim3 ggrid(HIDD / 128, NSEQ / 128, 3);   // 384 CTAs (zf interleaved)
    gemm3_tc_kernel<<<ggrid, 256, GEMM_SMEM>>>(bq, bk, bv, out);

    dim3 agrid(NSEQ / 128, NHEAD);           // 256 CTAs, 512 thr
    attn_mma_kernel<<<agrid, 512, ATTN_SMEM>>>(out);
}

// round 17
// speedup vs baseline: 1.5547x; 1.5547x over previous
#include <cuda_runtime.h>
#include <cuda_fp16.h>
#include <cstdint>

#define NSEQ  2048
#define HIDD  1024
#define NHEAD 16
#define HS    64
#define SAMPLED_ELEMS (16ULL * 2048ULL * 2048ULL)   // 67108864 floats
#define OUT4_TOTAL (SAMPLED_ELEMS / 4)              // 16777216 float4

// fp16 limb scratch
__device__ __half g_A0[3 * NSEQ * HIDD];
__device__ __half g_A1[3 * NSEQ * HIDD];
__device__ __half g_W0[3 * HIDD * HIDD];
__device__ __half g_W1[3 * HIDD * HIDD];
__device__ __half g_Q0[NSEQ * HIDD];
__device__ __half g_Q1[NSEQ * HIDD];
__device__ __half g_K0[NSEQ * HIDD];
__device__ __half g_K1[NSEQ * HIDD];

// ---------------- mma.sync / ldmatrix / cp.async helpers ----------------
__device__ __forceinline__ uint32_t smem_u32(const void* p) {
    uint32_t a;
    asm("{ .reg .u64 t; cvta.to.shared.u64 t, %1; cvt.u32.u64 %0, t; }" : "=r"(a) : "l"(p));
    return a;
}
__device__ __forceinline__ void ldsm4(uint32_t &r0, uint32_t &r1, uint32_t &r2,
                                      uint32_t &r3, uint32_t addr) {
    asm volatile("ldmatrix.sync.aligned.m8n8.x4.shared.b16 {%0,%1,%2,%3}, [%4];"
                 : "=r"(r0), "=r"(r1), "=r"(r2), "=r"(r3) : "r"(addr));
}
__device__ __forceinline__ void mma_f16(float &c0, float &c1, float &c2, float &c3,
                                        uint32_t a0, uint32_t a1, uint32_t a2, uint32_t a3,
                                        uint32_t b0, uint32_t b1) {
    asm volatile("mma.sync.aligned.m16n8k16.row.col.f32.f16.f16.f32 "
                 "{%0,%1,%2,%3}, {%4,%5,%6,%7}, {%8,%9}, {%0,%1,%2,%3};"
                 : "+f"(c0), "+f"(c1), "+f"(c2), "+f"(c3)
                 : "r"(a0), "r"(a1), "r"(a2), "r"(a3), "r"(b0), "r"(b1));
}
__device__ __forceinline__ void cp_async16(uint32_t dst, const void* src) {
    asm volatile("cp.async.cg.shared.global [%0], [%1], 16;" :: "r"(dst), "l"(src));
}
#define CP_COMMIT() asm volatile("cp.async.commit_group;" ::: "memory")
#define CP_WAIT0()  asm volatile("cp.async.wait_group 0;" ::: "memory")
#define CP_WAIT1()  asm volatile("cp.async.wait_group 1;" ::: "memory")

__device__ __forceinline__ void split16(float x, __half &h0, __half &h1) {
    h0 = __float2half(x);
    h1 = __float2half(x - __half2float(h0));
}

// =====================================================================
// Fused pre-pass: split activations + split/transpose weights.
// =====================================================================
__global__ void __launch_bounds__(256) split_all_kernel(
    const float* __restrict__ a0, const float* __restrict__ a1,
    const float* __restrict__ a2,
    const float* __restrict__ w0, const float* __restrict__ w1,
    const float* __restrict__ w2)
{
    const int bid = blockIdx.x;
    const int tid = threadIdx.x;

    if (bid < 6144) {
        const int mat = bid >> 11;
        const int row = bid & 2047;
        const float* src = (mat == 0) ? a0 : (mat == 1) ? a1 : a2;
        const size_t base = (size_t)mat * NSEQ * HIDD + (size_t)row * HIDD;
        float4 v = ((const float4*)(src + (size_t)row * HIDD))[tid];
        __half h0[4], h1[4];
        split16(v.x, h0[0], h1[0]);
        split16(v.y, h0[1], h1[1]);
        split16(v.z, h0[2], h1[2]);
        split16(v.w, h0[3], h1[3]);
        const size_t o = base + tid * 4;
        *(__half2*)&g_A0[o]     = __halves2half2(h0[0], h0[1]);
        *(__half2*)&g_A0[o + 2] = __halves2half2(h0[2], h0[3]);
        *(__half2*)&g_A1[o]     = __halves2half2(h1[0], h1[1]);
        *(__half2*)&g_A1[o + 2] = __halves2half2(h1[2], h1[3]);
    } else {
        __shared__ float t[32][33];
        const int wb = bid - 6144;
        const int mat = wb >> 10;
        const int rem = wb & 1023;
        const int n0 = (rem & 31) * 32, k0 = (rem >> 5) * 32;
        const float* W = (mat == 0) ? w0 : (mat == 1) ? w1 : w2;

        for (int i = tid; i < 1024; i += 256) {
            const int r = i >> 5, c = i & 31;
            t[r][c] = W[(size_t)(k0 + r) * HIDD + n0 + c];
        }
        __syncthreads();
        for (int i = tid; i < 1024; i += 256) {
            const int r = i >> 5, c = i & 31;
            const float x = t[c][r];
            __half h0, h1;
            split16(x, h0, h1);
            const size_t idx = (size_t)mat * HIDD * HIDD + (size_t)(n0 + r) * HIDD + k0 + c;
            g_W0[idx] = h0;
            g_W1[idx] = h1;
        }
    }
}

// =====================================================================
// Templated tensor-core GEMM + interleaved zero-fill slice.
// NLIMB/NPROD compile-time (fully unrolled, no spills):
//   Q,K: <2,3,6>  — fp16 2-limb, 3 products; 6 zf chunks/iter
//   V:   <1,1,4>  — single product a0*b0; 4 zf chunks/iter
// CTA 128x128, k-tile 32, triple-buffered cp.async.
// =====================================================================
#define GTILE 10240
#define GBUF  20480
#define GSTAGE 3
#define GEMM_SMEM (2 * GSTAGE * GBUF)    // 122880

template<int NLIMB, int NPROD, int ZPER>
__global__ void __launch_bounds__(256, 1) gemm_tc_kernel(
    const float* __restrict__ bq, const float* __restrict__ bk,
    const float* __restrict__ bv, float* __restrict__ out,
    int mat_base, uint32_t zbase, uint32_t zlimit)
{
    extern __shared__ char smem[];
    const uint32_t sb = smem_u32(smem);
    const int tid = threadIdx.x;
    const int lane = tid & 31, warp = tid >> 5;
    const int mat = mat_base + blockIdx.z;
    const int row0 = blockIdx.y * 128, col0 = blockIdx.x * 128;

    const __half* A0 = g_A0 + (size_t)mat * NSEQ * HIDD;
    const __half* A1 = g_A1 + (size_t)mat * NSEQ * HIDD;
    const __half* B0 = g_W0 + (size_t)mat * HIDD * HIDD;
    const __half* B1 = g_W1 + (size_t)mat * HIDD * HIDD;
    const float* bias = (mat == 0) ? bq : (mat == 1) ? bk : bv;
    float* Cv = out + SAMPLED_ELEMS;

    const uint32_t gtid = ((blockIdx.z * gridDim.y + blockIdx.y) * gridDim.x
                           + blockIdx.x) * 256 + tid;
    const uint32_t zstride = gridDim.x * gridDim.y * gridDim.z * 256;
    float4* o4 = (float4*)out;
    const float4 zval = make_float4(0.f, 0.f, 0.f, 0.f);

    auto load_tile = [&](int kt, int stage) {
        const int k0 = kt * 32;
#pragma unroll
        for (int s = 0; s < NLIMB; s++) {
            const __half* src = (s ? A1 : A0) + (size_t)row0 * HIDD + k0;
            const uint32_t dst = sb + stage * GBUF + s * GTILE;
            for (int i = tid; i < 512; i += 256) {
                const int r = i >> 2, c = i & 3;
                cp_async16(dst + r * 80 + c * 16, src + (size_t)r * HIDD + c * 8);
            }
        }
#pragma unroll
        for (int s = 0; s < NLIMB; s++) {
            const __half* src = (s ? B1 : B0) + (size_t)col0 * HIDD + k0;
            const uint32_t dst = sb + GSTAGE * GBUF + stage * GBUF + s * GTILE;
            for (int i = tid; i < 512; i += 256) {
                const int r = i >> 2, c = i & 3;
                cp_async16(dst + r * 80 + c * 16, src + (size_t)r * HIDD + c * 8);
            }
        }
        CP_COMMIT();
    };

    const int mwarp = warp >> 1, nwarp = warp & 1;
    const uint32_t a_lane = (lane & 15) * 80 + (lane >> 4) * 16;
    const uint32_t b_lane = ((lane & 7) + ((lane >> 4) << 3)) * 80 + ((lane >> 3) & 1) * 16;

    float acc[2][8][4];
#pragma unroll
    for (int mb = 0; mb < 2; mb++)
#pragma unroll
        for (int nb = 0; nb < 8; nb++)
#pragma unroll
            for (int e = 0; e < 4; e++) acc[mb][nb][e] = 0.0f;

    const int pa[3] = {0, 0, 1};
    const int pb[3] = {0, 1, 0};

    load_tile(0, 0);
    load_tile(1, 1);
    for (int t = 0; t < 32; t++) {
        const int stage = t % GSTAGE;
        CP_WAIT1();
        __syncthreads();
        if (t + 2 < 32) load_tile(t + 2, (t + 2) % GSTAGE);

        // interleaved streaming zero-fill slice
        {
            uint32_t zi = zbase + gtid + (uint32_t)t * ZPER * zstride;
#pragma unroll
            for (int z = 0; z < ZPER; z++) {
                if (zi < zlimit) __stcs(&o4[zi], zval);
                zi += zstride;
            }
        }

        const uint32_t Ab = sb + stage * GBUF;
        const uint32_t Bb = sb + GSTAGE * GBUF + stage * GBUF;
#pragma unroll
        for (int ks = 0; ks < 2; ks++) {
            uint32_t a[NLIMB][2][4];
#pragma unroll
            for (int s = 0; s < NLIMB; s++)
#pragma unroll
                for (int mb = 0; mb < 2; mb++)
                    ldsm4(a[s][mb][0], a[s][mb][1], a[s][mb][2], a[s][mb][3],
                          Ab + s * GTILE + (mwarp * 32 + mb * 16) * 80 + a_lane + ks * 32);
            uint32_t b[NLIMB][4][4];
#pragma unroll
            for (int s = 0; s < NLIMB; s++)
#pragma unroll
                for (int jj = 0; jj < 4; jj++)
                    ldsm4(b[s][jj][0], b[s][jj][1], b[s][jj][2], b[s][jj][3],
                          Bb + s * GTILE + (nwarp * 64 + jj * 16) * 80 + b_lane + ks * 32);
#pragma unroll
            for (int p = 0; p < NPROD; p++) {
#pragma unroll
                for (int mb = 0; mb < 2; mb++) {
                    const uint32_t* A = a[pa[p]][mb];
#pragma unroll
                    for (int jj = 0; jj < 4; jj++) {
                        mma_f16(acc[mb][2*jj][0], acc[mb][2*jj][1],
                                acc[mb][2*jj][2], acc[mb][2*jj][3],
                                A[0], A[1], A[2], A[3],
                                b[pb[p]][jj][0], b[pb[p]][jj][1]);
                        mma_f16(acc[mb][2*jj+1][0], acc[mb][2*jj+1][1],
                                acc[mb][2*jj+1][2], acc[mb][2*jj+1][3],
                                A[0], A[1], A[2], A[3],
                                b[pb[p]][jj][2], b[pb[p]][jj][3]);
                    }
                }
            }
        }
    }

    // ---- epilogue ----
    __half* S0 = (mat == 0) ? g_Q0 : g_K0;
    __half* S1 = (mat == 0) ? g_Q1 : g_K1;
#pragma unroll
    for (int mb = 0; mb < 2; mb++) {
        const int rbase = row0 + mwarp * 32 + mb * 16 + (lane >> 2);
#pragma unroll
        for (int hrow = 0; hrow < 2; hrow++) {
            const int r = rbase + hrow * 8;
#pragma unroll
            for (int nb = 0; nb < 8; nb++) {
                const int col = col0 + nwarp * 64 + nb * 8 + (lane & 3) * 2;
                const float2 bb = *(const float2*)&bias[col];
                const float x0 = acc[mb][nb][hrow * 2 + 0] + bb.x;
                const float x1 = acc[mb][nb][hrow * 2 + 1] + bb.y;
                if (mat == 2) {
                    *(float2*)&Cv[(size_t)r * HIDD + col] = make_float2(x0, x1);
                } else {
                    __half h00, h01, h10, h11;
                    split16(x0, h00, h01);
                    split16(x1, h10, h11);
                    const size_t idx = (size_t)r * HIDD + col;
                    *(__half2*)&S0[idx] = __halves2half2(h00, h10);
                    *(__half2*)&S1[idx] = __halves2half2(h01, h11);
                }
            }
        }
    }
}

// =====================================================================
// mma.sync attention: 512 threads (16 warps, 4/SMSP), 128 q rows/CTA.
// Warp (qw, kh): qw owns 16 q rows, kh owns 64 of 128 keys per tile.
// fp16 2-split, 3 products; double-buffered K via cp.async.
// Writes the one-hot 1.0 directly (zero-fill done earlier in-stream).
// =====================================================================
#define SPLIT_BYTES (128 * 144)
#define KBUF_BYTES  (2 * SPLIT_BYTES)     // 36864
#define ATTN_SMEM   (2 * KBUF_BYTES)      // 73728

__global__ void __launch_bounds__(512, 1) attn_mma_kernel(float* __restrict__ out)
{
    extern __shared__ char smem[];
    const uint32_t sb = smem_u32(smem);
    const int tid = threadIdx.x;
    const int lane = tid & 31, warp = tid >> 5;
    const int qw = warp >> 1, kh = warp & 1;
    const int h = blockIdx.y, q0 = blockIdx.x * 128;

    const __half* Qs[2] = {g_Q0 + (size_t)h * 131072 + (size_t)q0 * HS,
                           g_Q1 + (size_t)h * 131072 + (size_t)q0 * HS};
    const __half* Ks[2] = {g_K0 + (size_t)h * 131072,
                           g_K1 + (size_t)h * 131072};

#pragma unroll
    for (int s = 0; s < 2; s++) {
        for (int i = tid; i < 1024; i += 512) {
            const int row = i >> 3, c = i & 7;
            uint4 v = *(const uint4*)(Qs[s] + (size_t)row * HS + c * 8);
            *(uint4*)(smem + s * SPLIT_BYTES + row * 144 + c * 16) = v;
        }
    }
    __syncthreads();

    uint32_t afr[2][4][4];   // [split][ks][frag]
    {
        const uint32_t aoff = sb + (qw * 16 + (lane & 15)) * 144 + (lane >> 4) * 16;
#pragma unroll
        for (int s = 0; s < 2; s++)
#pragma unroll
            for (int ks = 0; ks < 4; ks++)
                ldsm4(afr[s][ks][0], afr[s][ks][1], afr[s][ks][2], afr[s][ks][3],
                      aoff + s * SPLIT_BYTES + ks * 32);
    }
    __syncthreads();

    auto load_k = [&](int kt, int buf) {
#pragma unroll
        for (int s = 0; s < 2; s++) {
            const __half* src = Ks[s] + (size_t)kt * 128 * HS;
            const uint32_t dst = sb + buf * KBUF_BYTES + s * SPLIT_BYTES;
            for (int i = tid; i < 1024; i += 512) {
                const int row = i >> 3, c = i & 7;
                cp_async16(dst + row * 144 + c * 16, src + (size_t)row * HS + c * 8);
            }
        }
        CP_COMMIT();
    };

    load_k(0, 0);
    CP_WAIT0();
    __syncthreads();

    const uint32_t boff_lane = ((lane & 7) + ((lane >> 4) << 3)) * 144
                             + (((lane >> 3) & 1)) * 16
                             + kh * 64 * 144;

    const int l4 = lane >> 2, l2 = (lane & 3) * 2;
    float best_lo = -__int_as_float(0x7f800000), best_hi = best_lo;
    int idx_lo = 0, idx_hi = 0;

    const int pa[3] = {0, 0, 1};
    const int pb[3] = {0, 1, 0};

    for (int kt = 0; kt < 16; kt++) {
        const int buf = kt & 1;
        if (kt < 15) load_k(kt + 1, buf ^ 1);

        float acc[8][4];
#pragma unroll
        for (int nb = 0; nb < 8; nb++)
#pragma unroll
            for (int e = 0; e < 4; e++) acc[nb][e] = 0.0f;

        const uint32_t bbase = sb + buf * KBUF_BYTES + boff_lane;

#pragma unroll
        for (int ks = 0; ks < 4; ks++) {
#pragma unroll
            for (int jh = 0; jh < 2; jh++) {
                uint32_t B[2][2][4];   // [split][jj][frag]
#pragma unroll
                for (int s = 0; s < 2; s++)
#pragma unroll
                    for (int jj = 0; jj < 2; jj++)
                        ldsm4(B[s][jj][0], B[s][jj][1], B[s][jj][2], B[s][jj][3],
                              bbase + s * SPLIT_BYTES + (jh * 2 + jj) * 16 * 144 + ks * 32);
#pragma unroll
                for (int p = 0; p < 3; p++) {
                    const uint32_t* A = afr[pa[p]][ks];
#pragma unroll
                    for (int jj = 0; jj < 2; jj++) {
                        const int j = jh * 2 + jj;
                        mma_f16(acc[2*j][0], acc[2*j][1], acc[2*j][2], acc[2*j][3],
                                A[0], A[1], A[2], A[3], B[pb[p]][jj][0], B[pb[p]][jj][1]);
                        mma_f16(acc[2*j+1][0], acc[2*j+1][1], acc[2*j+1][2], acc[2*j+1][3],
                                A[0], A[1], A[2], A[3], B[pb[p]][jj][2], B[pb[p]][jj][3]);
                    }
                }
            }
        }

#pragma unroll
        for (int nb = 0; nb < 8; nb++) {
            const int col = kt * 128 + kh * 64 + nb * 8 + l2;
            if (acc[nb][0] > best_lo) { best_lo = acc[nb][0]; idx_lo = col; }
            if (acc[nb][1] > best_lo) { best_lo = acc[nb][1]; idx_lo = col + 1; }
            if (acc[nb][2] > best_hi) { best_hi = acc[nb][2]; idx_hi = col; }
            if (acc[nb][3] > best_hi) { best_hi = acc[nb][3]; idx_hi = col + 1; }
        }

        if (kt < 15) { CP_WAIT0(); __syncthreads(); }
    }

#pragma unroll
    for (int off = 1; off <= 2; off <<= 1) {
        float v2 = __shfl_xor_sync(0xffffffffu, best_lo, off);
        int   i2 = __shfl_xor_sync(0xffffffffu, idx_lo, off);
        if (v2 > best_lo || (v2 == best_lo && i2 < idx_lo)) { best_lo = v2; idx_lo = i2; }
        v2 = __shfl_xor_sync(0xffffffffu, best_hi, off);
        i2 = __shfl_xor_sync(0xffffffffu, idx_hi, off);
        if (v2 > best_hi || (v2 == best_hi && i2 < idx_hi)) { best_hi = v2; idx_hi = i2; }
    }

    __syncthreads();
    float* sval = (float*)smem;               // [2][128]
    int*   sidx = (int*)(smem + 1024);        // [2][128]
    if ((lane & 3) == 0) {
        const int row = qw * 16 + l4;
        sval[kh * 128 + row]     = best_lo;
        sidx[kh * 128 + row]     = idx_lo;
        sval[kh * 128 + row + 8] = best_hi;
        sidx[kh * 128 + row + 8] = idx_hi;
    }
    __syncthreads();
    if (tid < 128) {
        const float v0 = sval[tid], v1 = sval[128 + tid];
        const int   i0 = sidx[tid], i1 = sidx[128 + tid];
        const int best = (v1 > v0 || (v1 == v0 && i1 < i0)) ? i1 : i0;
        out[((size_t)h * NSEQ + q0 + tid) * NSEQ + best] = 1.0f;
    }
}

// ---------------- launch (single stream, serial) ----------------
#define ZQK_LIMIT 12582912u    // 256 CTAs * 256 thr * 6 * 32
extern "C" void kernel_launch(void* const* d_in, const int* in_sizes, int n_in,
                              void* d_out, int out_size)
{
    const float* q_in = (const float*)d_in[0];
    const float* k_in = (const float*)d_in[1];
    const float* v_in = (const float*)d_in[2];
    const float* Wq   = (const float*)d_in[4];
    const float* bq   = (const float*)d_in[5];
    const float* Wk   = (const float*)d_in[6];
    const float* bk   = (const float*)d_in[7];
    const float* Wv   = (const float*)d_in[8];
    const float* bv   = (const float*)d_in[9];
    float* out = (float*)d_out;

    static bool init = false;
    if (!init) {
        cudaFuncSetAttribute(gemm_tc_kernel<2, 3, 6>,
                             cudaFuncAttributeMaxDynamicSharedMemorySize, GEMM_SMEM);
        cudaFuncSetAttribute(gemm_tc_kernel<1, 1, 4>,
                             cudaFuncAttributeMaxDynamicSharedMemorySize, GEMM_SMEM);
        cudaFuncSetAttribute(attn_mma_kernel,
                             cudaFuncAttributeMaxDynamicSharedMemorySize, ATTN_SMEM);
        init = true;
    }

    split_all_kernel<<<9216, 256>>>(q_in, k_in, v_in, Wq, Wk, Wv);

    // Q,K gemm: 2-limb, 3 products; zero-fills first 12.58M float4
    dim3 gqk(HIDD / 128, NSEQ / 128, 2);     // 256 CTAs
    gemm_tc_kernel<2, 3, 6><<<gqk, 256, GEMM_SMEM>>>(bq, bk, bv, out, 0,
                                                     0u, ZQK_LIMIT);

    // V gemm: 1-limb, 1 product; zero-fills the remaining 4.19M float4
    dim3 gv(HIDD / 128, NSEQ / 128, 1);      // 128 CTAs
    gemm_tc_kernel<1, 1, 4><<<gv, 256, GEMM_SMEM>>>(bq, bk, bv, out, 2,
                                                    ZQK_LIMIT, OUT4_TOTAL);

    dim3 agrid(NSEQ / 128, NHEAD);           // 256 CTAs, 512 thr
    attn_mma_kernel<<<agrid, 512, ATTN_SMEM>>>(out);
}